// round 1
// baseline (speedup 1.0000x reference)
#include <cuda_runtime.h>

#define IMG_H 512
#define IMG_W 512
#define HW (IMG_H * IMG_W)

// Fused bilateral-grid pipeline: one thread per pixel.
// guide1 -> slice(grid1) -> affine+relu -> guide2 -> slice(grid2) -> affine
__global__ __launch_bounds__(256) void bgrid_fused_kernel(
    const float* __restrict__ src,    // (8,3,512,512)
    const float* __restrict__ grid1,  // (8,32,8,16,16)
    const float* __restrict__ grid2,  // (8,27,8,16,16)
    const float* __restrict__ w1,     // (16,3)
    const float* __restrict__ b1,     // (16)
    const float* __restrict__ w2,     // (16)
    const float* __restrict__ b2,     // (1)
    const float* __restrict__ w3,     // (16,8)
    const float* __restrict__ b3,     // (16)
    const float* __restrict__ w4,     // (16)
    const float* __restrict__ b4,     // (1)
    float* __restrict__ out)          // (8,3,512,512)
{
    __shared__ float sw1[48];
    __shared__ float sb1[16];
    __shared__ float sw2[16];
    __shared__ float sw3[128];
    __shared__ float sb3[16];
    __shared__ float sw4[16];
    __shared__ float sb2s, sb4s;

    const int tid = threadIdx.x;
    if (tid < 48)  sw1[tid] = w1[tid];
    if (tid < 16) {
        sb1[tid] = b1[tid];
        sw2[tid] = w2[tid];
        sb3[tid] = b3[tid];
        sw4[tid] = w4[tid];
    }
    if (tid < 128) sw3[tid] = w3[tid];
    if (tid == 0) { sb2s = b2[0]; sb4s = b4[0]; }
    __syncthreads();

    const int idx = blockIdx.x * 256 + tid;     // 0 .. 8*512*512-1
    const int px = idx & 511;                   // w
    const int py = (idx >> 9) & 511;            // h
    const int pb = idx >> 18;                   // batch

    // ---- load src pixel (3 channels) ----
    const float* srcp = src + (pb * 3) * HW + py * IMG_W + px;
    const float s0 = srcp[0];
    const float s1 = srcp[HW];
    const float s2 = srcp[2 * HW];

    // ---- guide NN #1: 3 -> 16 -> 1, relu then tanh ----
    float g = sb2s;
#pragma unroll
    for (int o = 0; o < 16; o++) {
        float t = sb1[o];
        t = fmaf(sw1[o * 3 + 0], s0, t);
        t = fmaf(sw1[o * 3 + 1], s1, t);
        t = fmaf(sw1[o * 3 + 2], s2, t);
        t = fmaxf(t, 0.0f);
        g = fmaf(sw2[o], t, g);
    }
    g = tanhf(g);

    // ---- xy lattice coords (shared by both slices; Gh=Gw=16, D=8) ----
    const float fx = (float)px * (15.0f / 512.0f);   // in [0, 14.97]
    const float fy = (float)py * (15.0f / 512.0f);
    const int x0 = (int)fx;
    const int x1 = min(x0 + 1, 15);
    const int y0 = (int)fy;
    const int y1 = min(y0 + 1, 15);
    const float wx = fx - (float)x0;
    const float wy = fy - (float)y0;
    const float w00 = (1.0f - wy) * (1.0f - wx);
    const float w01 = (1.0f - wy) * wx;
    const float w10 = wy * (1.0f - wx);
    const float w11 = wy * wx;
    const int o00 = y0 * 16 + x0;
    const int o01 = y0 * 16 + x1;
    const int o10 = y1 * 16 + x0;
    const int o11 = y1 * 16 + x1;

    // ---- z coords for slice 1 ----
    float fz = fminf(fmaxf((g + 1.0f) * 0.5f * 7.0f, 0.0f), 7.0f);
    int z0 = (int)fz;
    if (z0 > 7) z0 = 7;
    int z1 = min(z0 + 1, 7);
    float wz = fz - (float)z0;
    int zo0 = z0 * 256;
    int zo1 = z1 * 256;

    // ---- slice grid1 (32 channels) and fold directly into hidden[8] ----
    // coeff1 reshape (4,8) transpose -> hidden[k] gets channels {k, 8+k, 16+k, 24+k}
    float hid[8];
#pragma unroll
    for (int k = 0; k < 8; k++) hid[k] = 0.0f;

    const float* g1b = grid1 + pb * (32 * 2048);
#pragma unroll
    for (int c = 0; c < 32; c++) {
        const float* gc = g1b + c * 2048;
        float v0 = __ldg(gc + zo0 + o00) * w00;
        v0 = fmaf(__ldg(gc + zo0 + o01), w01, v0);
        v0 = fmaf(__ldg(gc + zo0 + o10), w10, v0);
        v0 = fmaf(__ldg(gc + zo0 + o11), w11, v0);
        float v1 = __ldg(gc + zo1 + o00) * w00;
        v1 = fmaf(__ldg(gc + zo1 + o01), w01, v1);
        v1 = fmaf(__ldg(gc + zo1 + o10), w10, v1);
        v1 = fmaf(__ldg(gc + zo1 + o11), w11, v1);
        const float v = fmaf(wz, v1 - v0, v0);
        const int k = c & 7;
        const int a = c >> 3;
        if (a == 0)      hid[k] = fmaf(v, s0, hid[k]);
        else if (a == 1) hid[k] = fmaf(v, s1, hid[k]);
        else if (a == 2) hid[k] = fmaf(v, s2, hid[k]);
        else             hid[k] += v;
    }
#pragma unroll
    for (int k = 0; k < 8; k++) hid[k] = fmaxf(hid[k], 0.0f);

    // ---- guide NN #2: 8 -> 16 -> 1 ----
    float g2 = sb4s;
#pragma unroll
    for (int o = 0; o < 16; o++) {
        float t = sb3[o];
#pragma unroll
        for (int p = 0; p < 8; p++) t = fmaf(sw3[o * 8 + p], hid[p], t);
        t = fmaxf(t, 0.0f);
        g2 = fmaf(sw4[o], t, g2);
    }
    g2 = tanhf(g2);

    // ---- z coords for slice 2 ----
    fz = fminf(fmaxf((g2 + 1.0f) * 0.5f * 7.0f, 0.0f), 7.0f);
    z0 = (int)fz;
    if (z0 > 7) z0 = 7;
    z1 = min(z0 + 1, 7);
    wz = fz - (float)z0;
    zo0 = z0 * 256;
    zo1 = z1 * 256;

    // ---- slice grid2 (27 channels) and fold into out[3] ----
    // coeff2 reshape (9,3) transpose -> out[q] gets channels {q, 3+q, ..., 24+q}
    float r0 = 0.0f, r1 = 0.0f, r2 = 0.0f;
    const float* g2b = grid2 + pb * (27 * 2048);
#pragma unroll
    for (int c = 0; c < 27; c++) {
        const float* gc = g2b + c * 2048;
        float v0 = __ldg(gc + zo0 + o00) * w00;
        v0 = fmaf(__ldg(gc + zo0 + o01), w01, v0);
        v0 = fmaf(__ldg(gc + zo0 + o10), w10, v0);
        v0 = fmaf(__ldg(gc + zo0 + o11), w11, v0);
        float v1 = __ldg(gc + zo1 + o00) * w00;
        v1 = fmaf(__ldg(gc + zo1 + o01), w01, v1);
        v1 = fmaf(__ldg(gc + zo1 + o10), w10, v1);
        v1 = fmaf(__ldg(gc + zo1 + o11), w11, v1);
        const float v = fmaf(wz, v1 - v0, v0);
        const int q = c % 3;   // output channel
        const int p = c / 3;   // input (hidden) channel, 8 = bias
        const float m = (p < 8) ? hid[p] : 1.0f;
        if (q == 0)      r0 = fmaf(v, m, r0);
        else if (q == 1) r1 = fmaf(v, m, r1);
        else             r2 = fmaf(v, m, r2);
    }

    float* outp = out + (pb * 3) * HW + py * IMG_W + px;
    outp[0]      = r0;
    outp[HW]     = r1;
    outp[2 * HW] = r2;
}

extern "C" void kernel_launch(void* const* d_in, const int* in_sizes, int n_in,
                              void* d_out, int out_size) {
    const float* src   = (const float*)d_in[0];
    const float* grid1 = (const float*)d_in[1];
    const float* grid2 = (const float*)d_in[2];
    const float* w1    = (const float*)d_in[3];
    const float* b1    = (const float*)d_in[4];
    const float* w2    = (const float*)d_in[5];
    const float* b2    = (const float*)d_in[6];
    const float* w3    = (const float*)d_in[7];
    const float* b3    = (const float*)d_in[8];
    const float* w4    = (const float*)d_in[9];
    const float* b4    = (const float*)d_in[10];
    float* out = (float*)d_out;

    const int total = 8 * IMG_H * IMG_W;           // 2,097,152 pixels
    const int threads = 256;
    const int blocks = total / threads;            // 8192
    bgrid_fused_kernel<<<blocks, threads>>>(src, grid1, grid2,
                                            w1, b1, w2, b2, w3, b3, w4, b4,
                                            out);
}